// round 14
// baseline (speedup 1.0000x reference)
#include <cuda_runtime.h>
#include <cstdint>

// KDE via int8 mma.sync m16n8k32 tensor-core GEMM, 2-level Ozaki split
// (4 exact integer product-GEMMs, Horner-combined in fp32), fused exp
// epilogue, deterministic fixed-order reduction.
//
// density[n] = (1/M) * sum_m exp( (2*dot(x_n,d_m) - |x_n|^2 - |d_m|^2) * C )
// x_row = sx*(q1 + q2/256) + r2,  |r2| <= sx/512  (per-row scale sx)
// dot   = sx*sd*( S11 + (S12+S21)/256 + S22/65536 ) + O(r2)

#define DDIM   128
#define BM     128
#define BN     128
#define PITCHB 144            // smem row pitch bytes for 128B rows (ldmatrix conflict-free)
#define TILEB  (128 * PITCHB) // 18432 per tile
#define MAXROWS 8192
#define NCHUNK  256           // (M/128)*4 column chunks of 32

#define CC   0.19947114020071633897f   // 0.5/sqrt(2*pi)
#define TWOC 0.39894228040143267794f

__device__ __align__(256) int8_t g_xq[MAXROWS * 256];  // per row: [q1 128B | q2 128B]
__device__ __align__(256) int8_t g_dq[MAXROWS * 256];
__device__ float g_xn[MAXROWS], g_dn[MAXROWS];         // exact fp32 norms
__device__ float g_sx[MAXROWS], g_sd[MAXROWS];         // per-row scales
__device__ float g_part[NCHUNK * MAXROWS];

// ---------------------------------------------------------------------------
__device__ __forceinline__ uint32_t smem_u32(const void* p) {
    uint32_t a;
    asm("{ .reg .u64 t; cvta.to.shared.u64 t, %1; cvt.u32.u64 %0, t; }"
        : "=r"(a) : "l"(p));
    return a;
}
__device__ __forceinline__ void cp16(uint32_t dst, const void* src) {
    asm volatile("cp.async.cg.shared.global [%0], [%1], 16;"
                 :: "r"(dst), "l"(src) : "memory");
}
__device__ __forceinline__ void ldmx4(uint32_t* r, uint32_t addr) {
    asm volatile("ldmatrix.sync.aligned.m8n8.x4.shared.b16 {%0,%1,%2,%3}, [%4];"
                 : "=r"(r[0]), "=r"(r[1]), "=r"(r[2]), "=r"(r[3]) : "r"(addr));
}
__device__ __forceinline__ void mma_s8(int* c, const uint32_t* a,
                                       uint32_t b0, uint32_t b1) {
    asm volatile(
        "mma.sync.aligned.m16n8k32.row.col.s32.s8.s8.s32 "
        "{%0,%1,%2,%3}, {%4,%5,%6,%7}, {%8,%9}, {%0,%1,%2,%3};"
        : "+r"(c[0]), "+r"(c[1]), "+r"(c[2]), "+r"(c[3])
        : "r"(a[0]), "r"(a[1]), "r"(a[2]), "r"(a[3]), "r"(b0), "r"(b1));
}
__device__ __forceinline__ int q8(float v) {
    int q = __float2int_rn(v);
    return max(-127, min(127, q));
}

// ---------------------------------------------------------------------------
// Kernel 1: per-row 2-level int8 quantization + exact fp32 norms + scales.
// One warp per row; lane handles one float4.
// ---------------------------------------------------------------------------
__global__ __launch_bounds__(256)
void prep_kernel(const float* __restrict__ x, const float* __restrict__ dat,
                 int N, int M) {
    int w = (blockIdx.x * blockDim.x + threadIdx.x) >> 5;
    int lane = threadIdx.x & 31;
    int R = (N > M) ? N : M;
    if (w >= R) return;

    #pragma unroll
    for (int which = 0; which < 2; which++) {
        if ((which ? M : N) <= w) continue;
        const float* src = which ? dat : x;
        float4 v = ((const float4*)(src + (size_t)w * DDIM))[lane];

        float mx = fmaxf(fmaxf(fabsf(v.x), fabsf(v.y)),
                         fmaxf(fabsf(v.z), fabsf(v.w)));
        #pragma unroll
        for (int o = 16; o > 0; o >>= 1)
            mx = fmaxf(mx, __shfl_xor_sync(0xFFFFFFFFu, mx, o));
        float s   = (mx > 0.f) ? mx * (1.0f / 127.0f) : 1.0f;
        float inv = 1.0f / s;

        int a1 = q8(v.x * inv), b1 = q8(v.y * inv),
            c1 = q8(v.z * inv), d1 = q8(v.w * inv);
        int a2 = q8((v.x - s * a1) * inv * 256.0f);
        int b2 = q8((v.y - s * b1) * inv * 256.0f);
        int c2 = q8((v.z - s * c1) * inv * 256.0f);
        int d2 = q8((v.w - s * d1) * inv * 256.0f);
        uint32_t u1 = (a1 & 255) | ((b1 & 255) << 8) |
                      ((c1 & 255) << 16) | ((d1 & 255) << 24);
        uint32_t u2 = (a2 & 255) | ((b2 & 255) << 8) |
                      ((c2 & 255) << 16) | ((d2 & 255) << 24);
        uint32_t* row = (uint32_t*)((which ? g_dq : g_xq) + (size_t)w * 256);
        row[lane] = u1;           // level-1 bytes [0,128)
        row[32 + lane] = u2;      // level-2 bytes [128,256)

        float sn = v.x * v.x + v.y * v.y + v.z * v.z + v.w * v.w;
        #pragma unroll
        for (int o = 16; o > 0; o >>= 1)
            sn += __shfl_down_sync(0xFFFFFFFFu, sn, o);
        if (lane == 0) {
            if (which) { g_dn[w] = sn; g_sd[w] = s; }
            else       { g_xn[w] = sn; g_sx[w] = s; }
        }
    }
}

// ---------------------------------------------------------------------------
// Kernel 2: 128x128 tile per CTA, 512 threads = 16 warps (4M x 4N grid),
// warp tile 32x32. All 4 int8 tiles (A1,A2,B1,B2) loaded once; product
// order (2,2) -> (1,2)+(2,1) -> (1,1) with Horner fp32 folding.
// ---------------------------------------------------------------------------
#define SO_DNS 0                       // 128 f: -dn*C
#define SO_SD  512                     // 128 f: sd
#define SO_T   1024                    // tiles: A1,A2,B1,B2 (TILEB each)
#define SMEMT  (SO_T + 4 * TILEB)      // 74752 B

__global__ __launch_bounds__(512, 1)
void kde_mma(int N, int M) {
    extern __shared__ char smem[];
    const uint32_t sb = smem_u32(smem);
    const int tid = threadIdx.x, lane = tid & 31, w = tid >> 5;
    const int wm = w >> 2, wn = w & 3;
    const int rowBase = blockIdx.y * BM;
    const int colBase = blockIdx.x * BN;

    if (tid < 128) {
        *(float*)(smem + SO_DNS + tid * 4) = -g_dn[colBase + tid] * CC;
        *(float*)(smem + SO_SD  + tid * 4) =  g_sd[colBase + tid];
    }

    const int8_t* Ag = g_xq + (size_t)rowBase * 256;
    const int8_t* Bg = g_dq + (size_t)colBase * 256;

    // Load: each tile = 128 rows x 128B = 1024 16B-chunks, 2 per thread.
    auto ldtile = [&](uint32_t dstBase, const int8_t* src) {
        #pragma unroll
        for (int i = 0; i < 2; i++) {
            int f = tid + i * 512, r = f >> 3, q = f & 7;
            cp16(dstBase + r * PITCHB + q * 16, src + (size_t)r * 256 + q * 16);
        }
    };
    // group0 = level-2 tiles (needed first), group1 = level-1 tiles
    ldtile(sb + SO_T + 1 * TILEB, Ag + 128);   // A2
    ldtile(sb + SO_T + 3 * TILEB, Bg + 128);   // B2
    asm volatile("cp.async.commit_group;" ::: "memory");
    ldtile(sb + SO_T + 0 * TILEB, Ag);         // A1
    ldtile(sb + SO_T + 2 * TILEB, Bg);         // B1
    asm volatile("cp.async.commit_group;" ::: "memory");

    // ldmatrix lane offsets (identical byte semantics to the bf16 kernel)
    const int bq = lane >> 3, rr = lane & 7;
    const uint32_t aLane = (uint32_t)(((bq & 1) * 8 + rr) * PITCHB + (lane >> 4) * 16);
    const uint32_t bLane = (uint32_t)((((lane >> 4) * 8) + rr) * PITCHB + (bq & 1) * 16);
    const uint32_t aOff = (uint32_t)(wm * 32 * PITCHB) + aLane;
    const uint32_t bOff = (uint32_t)(wn * 32 * PITCHB) + bLane;
    const uint32_t tA1 = sb + SO_T + 0 * TILEB + aOff;
    const uint32_t tA2 = sb + SO_T + 1 * TILEB + aOff;
    const uint32_t tB1 = sb + SO_T + 2 * TILEB + bOff;
    const uint32_t tB2 = sb + SO_T + 3 * TILEB + bOff;

    int   S[2][4][4];
    float F[2][4][4];
    #pragma unroll
    for (int h = 0; h < 2; h++)
        #pragma unroll
        for (int j = 0; j < 4; j++)
            #pragma unroll
            for (int k = 0; k < 4; k++) S[h][j][k] = 0;

    // one product-GEMM: K=128 int8 = 4 k32 steps, 8 mma each
    auto product = [&](uint32_t ab, uint32_t bb) {
        #pragma unroll
        for (int ks = 0; ks < 4; ks++) {
            uint32_t a0[4], a1[4], b0[4], b1[4];
            ldmx4(a0, ab + ks * 32);
            ldmx4(a1, ab + 16 * PITCHB + ks * 32);
            ldmx4(b0, bb + ks * 32);
            ldmx4(b1, bb + 16 * PITCHB + ks * 32);
            mma_s8(S[0][0], a0, b0[0], b0[1]);
            mma_s8(S[0][1], a0, b0[2], b0[3]);
            mma_s8(S[0][2], a0, b1[0], b1[1]);
            mma_s8(S[0][3], a0, b1[2], b1[3]);
            mma_s8(S[1][0], a1, b0[0], b0[1]);
            mma_s8(S[1][1], a1, b0[2], b0[3]);
            mma_s8(S[1][2], a1, b1[0], b1[1]);
            mma_s8(S[1][3], a1, b1[2], b1[3]);
        }
    };

    asm volatile("cp.async.wait_group 1;" ::: "memory");
    __syncthreads();
    product(tA2, tB2);                      // S22 (level-1 tiles still loading)
    #pragma unroll
    for (int h = 0; h < 2; h++)
        #pragma unroll
        for (int j = 0; j < 4; j++)
            #pragma unroll
            for (int k = 0; k < 4; k++) {
                F[h][j][k] = (float)S[h][j][k]; S[h][j][k] = 0;
            }

    asm volatile("cp.async.wait_group 0;" ::: "memory");
    __syncthreads();
    product(tA1, tB2);                      // S12  (same weight ->
    product(tA2, tB1);                      //  S21  shared s32 acc)
    #pragma unroll
    for (int h = 0; h < 2; h++)
        #pragma unroll
        for (int j = 0; j < 4; j++)
            #pragma unroll
            for (int k = 0; k < 4; k++) {
                F[h][j][k] = F[h][j][k] * (1.0f / 256.0f) + (float)S[h][j][k];
                S[h][j][k] = 0;
            }
    product(tA1, tB1);                      // S11
    #pragma unroll
    for (int h = 0; h < 2; h++)
        #pragma unroll
        for (int j = 0; j < 4; j++)
            #pragma unroll
            for (int k = 0; k < 4; k++)
                F[h][j][k] = F[h][j][k] * (1.0f / 256.0f) + (float)S[h][j][k];

    // Epilogue: e = F*(2C*sx*sd) - xn*C - dn*C ; sum exp over warp's 32 cols.
    const float* dnsS = (const float*)(smem + SO_DNS);
    const float* sdS  = (const float*)(smem + SO_SD);
    #pragma unroll
    for (int h = 0; h < 2; h++) {
        const int rA = rowBase + wm * 32 + h * 16 + (lane >> 2);
        const int rB = rA + 8;
        const float wA = TWOC * g_sx[rA], xnA = -g_xn[rA] * CC;
        const float wB = TWOC * g_sx[rB], xnB = -g_xn[rB] * CC;
        float s0 = 0.f, s1 = 0.f;
        #pragma unroll
        for (int j = 0; j < 4; j++) {
            const int cl = wn * 32 + j * 8 + 2 * (lane & 3);
            const float sd0 = sdS[cl], sd1 = sdS[cl + 1];
            const float dn0 = dnsS[cl], dn1 = dnsS[cl + 1];
            s0 += __expf(fmaf(F[h][j][0], wA * sd0, xnA + dn0));
            s0 += __expf(fmaf(F[h][j][1], wA * sd1, xnA + dn1));
            s1 += __expf(fmaf(F[h][j][2], wB * sd0, xnB + dn0));
            s1 += __expf(fmaf(F[h][j][3], wB * sd1, xnB + dn1));
        }
        s0 += __shfl_xor_sync(0xFFFFFFFFu, s0, 1);
        s0 += __shfl_xor_sync(0xFFFFFFFFu, s0, 2);
        s1 += __shfl_xor_sync(0xFFFFFFFFu, s1, 1);
        s1 += __shfl_xor_sync(0xFFFFFFFFu, s1, 2);
        if ((lane & 3) == 0) {
            const size_t chunk = blockIdx.x * 4 + wn;   // 256 chunks of 32 cols
            g_part[chunk * N + rA] = s0;
            g_part[chunk * N + rB] = s1;
        }
    }
}

// ---------------------------------------------------------------------------
// Kernel 3: fixed-order reduction over 256 column chunks -> density.
// ---------------------------------------------------------------------------
__global__ void reduce_kernel(float* __restrict__ out, int N, int M, int nchunk) {
    int r = blockIdx.x * blockDim.x + threadIdx.x;
    if (r >= N) return;
    float s = 0.f;
    for (int t = 0; t < nchunk; t++) s += g_part[(size_t)t * N + r];
    out[r] = s * (1.0f / (float)M);
}

// ---------------------------------------------------------------------------
extern "C" void kernel_launch(void* const* d_in, const int* in_sizes, int n_in,
                              void* d_out, int out_size) {
    const float* x   = (const float*)d_in[0];
    const float* dat = (const float*)d_in[1];
    float* out = (float*)d_out;

    int N = in_sizes[0] / DDIM;   // 8192
    int M = in_sizes[1] / DDIM;   // 8192
    int R = (N > M) ? N : M;

    cudaFuncSetAttribute(kde_mma, cudaFuncAttributeMaxDynamicSharedMemorySize,
                         SMEMT);

    prep_kernel<<<(R * 32 + 255) / 256, 256>>>(x, dat, N, M);

    dim3 grid(M / BN, N / BM);    // (64, 64) = 4096 CTAs
    kde_mma<<<grid, 512, SMEMT>>>(N, M);

    reduce_kernel<<<(N + 255) / 256, 256>>>(out, N, M, M / 32);
}

// round 16
// speedup vs baseline: 4.0286x; 4.0286x over previous
#include <cuda_runtime.h>
#include <cuda_fp16.h>
#include <cstdint>

// KDE via mma.sync fp16 tensor-core GEMM, one-sided Dekker 2-split folded
// into K=256 ( Xa=[xhi|xlo], Da=[dhi|dhi] -> dot = x . dhi exactly ),
// triple-buffered cp.async pipeline (one barrier per stage), fused exp
// epilogue, deterministic fixed-order reduction.
//
// density[n] = (1/M) * sum_m exp( (2*dot(x_n,d_m) - |x_n|^2 - |d_m|^2) * C )

#define DDIM   128
#define KAUG   256            // [xhi|xlo] x [dhi|dhi]
#define BM     128            // x rows per CTA
#define BN     256            // data rows per CTA
#define BKB    64             // fp16 K per stage
#define NST    (KAUG / BKB)   // 4
#define PITCHB 144            // smem row pitch bytes (72 halfs)
#define MAXROWS 8192
#define MAXCHUNK 128

#define CC  0.19947114020071633897f    // 0.5 / sqrt(2*pi)

__device__ __align__(256) __half g_xa[MAXROWS * KAUG];  // 4.2 MB
__device__ __align__(256) __half g_da[MAXROWS * KAUG];
__device__ float g_xn[MAXROWS];
__device__ float g_dn[MAXROWS];
__device__ float g_part[MAXCHUNK * MAXROWS];

// ---------------------------------------------------------------------------
__device__ __forceinline__ uint32_t smem_u32(const void* p) {
    uint32_t a;
    asm("{ .reg .u64 t; cvta.to.shared.u64 t, %1; cvt.u32.u64 %0, t; }"
        : "=r"(a) : "l"(p));
    return a;
}
__device__ __forceinline__ void cp16(uint32_t dst, const void* src) {
    asm volatile("cp.async.cg.shared.global [%0], [%1], 16;"
                 :: "r"(dst), "l"(src) : "memory");
}
__device__ __forceinline__ void ldmx4(uint32_t* r, uint32_t addr) {
    asm volatile("ldmatrix.sync.aligned.m8n8.x4.shared.b16 {%0,%1,%2,%3}, [%4];"
                 : "=r"(r[0]), "=r"(r[1]), "=r"(r[2]), "=r"(r[3]) : "r"(addr));
}
__device__ __forceinline__ void mma_f16(float* c, const uint32_t* a,
                                        uint32_t b0, uint32_t b1) {
    asm volatile(
        "mma.sync.aligned.m16n8k16.row.col.f32.f16.f16.f32 "
        "{%0,%1,%2,%3}, {%4,%5,%6,%7}, {%8,%9}, {%0,%1,%2,%3};"
        : "+f"(c[0]), "+f"(c[1]), "+f"(c[2]), "+f"(c[3])
        : "r"(a[0]), "r"(a[1]), "r"(a[2]), "r"(a[3]), "r"(b0), "r"(b1));
}
__device__ __forceinline__ uint32_t packh2(float a, float b) {
    __half2 p = __floats2half2_rn(a, b);
    return *reinterpret_cast<uint32_t*>(&p);
}

// ---------------------------------------------------------------------------
// Kernel 1: fp16 hi/lo Dekker split into augmented matrices + fp32 norms.
// One warp per row; lane handles one float4.
// ---------------------------------------------------------------------------
__global__ __launch_bounds__(256)
void prep_kernel(const float* __restrict__ x, const float* __restrict__ dat,
                 int N, int M) {
    int w = (blockIdx.x * blockDim.x + threadIdx.x) >> 5;
    int lane = threadIdx.x & 31;
    int R = (N > M) ? N : M;
    if (w >= R) return;

    #pragma unroll
    for (int which = 0; which < 2; which++) {
        if ((which ? M : N) <= w) continue;
        const float* src = which ? dat : x;
        float4 v = ((const float4*)(src + (size_t)w * DDIM))[lane];

        float hx = __half2float(__float2half_rn(v.x));
        float hy = __half2float(__float2half_rn(v.y));
        float hz = __half2float(__float2half_rn(v.z));
        float hw = __half2float(__float2half_rn(v.w));
        uint2 hi = make_uint2(packh2(v.x, v.y), packh2(v.z, v.w));
        uint2 lo = make_uint2(packh2(v.x - hx, v.y - hy),
                              packh2(v.z - hz, v.w - hw));
        uint2* dst = (uint2*)((which ? g_da : g_xa) + (size_t)w * KAUG) + lane;
        if (which == 0) {            // X: [hi | lo]  (exact split of x)
            dst[0] = hi; dst[32] = lo;
        } else {                     // D: [hi | hi]
            dst[0] = hi; dst[32] = hi;
        }
        float s = v.x * v.x + v.y * v.y + v.z * v.z + v.w * v.w;
        #pragma unroll
        for (int o = 16; o > 0; o >>= 1) s += __shfl_down_sync(0xFFFFFFFFu, s, o);
        if (lane == 0) { if (which) g_dn[w] = s; else g_xn[w] = s; }
    }
}

// ---------------------------------------------------------------------------
// Kernel 2: 128x256 tile per CTA, 512 threads = 16 warps (4 M x 4 N),
// warp tile 32x64. Triple-buffered cp.async (depth 2), ONE sync per stage.
// ---------------------------------------------------------------------------
#define SO_DNS 0
#define SA_BYTES (128 * PITCHB)            // 18432
#define SB_BYTES (256 * PITCHB)            // 36864
#define SO_A   1024
#define SO_B   (SO_A + 3 * SA_BYTES)       // 56320
#define SMEMT  (SO_B + 3 * SB_BYTES)       // 166912 B (1 CTA/SM)

__global__ __launch_bounds__(512, 1)
void kde_mma(int N, int M) {
    extern __shared__ char smem[];
    const uint32_t sb = smem_u32(smem);
    const int tid = threadIdx.x, lane = tid & 31, w = tid >> 5;
    const int wm = w >> 2, wn = w & 3;
    const int rowBase = blockIdx.y * BM;
    const int colBase = blockIdx.x * BN;

    if (tid < 256)
        *(float*)(smem + SO_DNS + tid * 4) = -g_dn[colBase + tid] * CC;

    const __half* Ag = g_xa + (size_t)rowBase * KAUG;
    const __half* Bg = g_da + (size_t)colBase * KAUG;

    float acc[2][8][4];
    #pragma unroll
    for (int i = 0; i < 2; i++)
        #pragma unroll
        for (int j = 0; j < 8; j++)
            #pragma unroll
            for (int c = 0; c < 4; c++) acc[i][j][c] = 0.f;

    // ldmatrix lane address bases (buffer 0)
    const int bq = lane >> 3, rr = lane & 7;
    const uint32_t aAddr0 = sb + SO_A +
        (uint32_t)((wm * 32 + (bq & 1) * 8 + rr) * PITCHB) + (uint32_t)((lane >> 4) * 16);
    const uint32_t bAddr0 = sb + SO_B +
        (uint32_t)((wn * 64 + (lane >> 4) * 8 + rr) * PITCHB) + (uint32_t)((bq & 1) * 16);

    // cp.async stage issue: A = 1024 x16B (2/thread), B = 2048 x16B (4/thread)
    auto issue = [&](int s) {
        const int kb = s * BKB;
        const int buf = s % 3;
        const uint32_t ab = sb + SO_A + buf * SA_BYTES;
        const uint32_t bb = sb + SO_B + buf * SB_BYTES;
        #pragma unroll
        for (int i = 0; i < 2; i++) {
            int f = tid + i * 512, r = f >> 3, q = f & 7;
            cp16(ab + r * PITCHB + q * 16, Ag + (size_t)r * KAUG + kb + q * 8);
        }
        #pragma unroll
        for (int i = 0; i < 4; i++) {
            int f = tid + i * 512, r = f >> 3, q = f & 7;
            cp16(bb + r * PITCHB + q * 16, Bg + (size_t)r * KAUG + kb + q * 8);
        }
        asm volatile("cp.async.commit_group;" ::: "memory");
    };

    issue(0);
    issue(1);
    for (int s = 0; s < NST; s++) {
        if (s < NST - 1)
            asm volatile("cp.async.wait_group 1;" ::: "memory");
        else
            asm volatile("cp.async.wait_group 0;" ::: "memory");
        __syncthreads();
        if (s + 2 < NST) issue(s + 2);   // overlaps this stage's compute

        const int buf = s % 3;
        const uint32_t ab = aAddr0 + buf * SA_BYTES;
        const uint32_t bb = bAddr0 + buf * SB_BYTES;
        #pragma unroll
        for (int k4 = 0; k4 < BKB / 16; k4++) {      // 4 k16 steps
            uint32_t a0[4], a1[4];
            ldmx4(a0, ab + k4 * 32);                 // m rows +0..15
            ldmx4(a1, ab + 16 * PITCHB + k4 * 32);   // m rows +16..31
            #pragma unroll
            for (int jj = 0; jj < 4; jj++) {         // 16 n each
                uint32_t b[4];
                ldmx4(b, bb + jj * 16 * PITCHB + k4 * 32);
                mma_f16(acc[0][2 * jj],     a0, b[0], b[1]);
                mma_f16(acc[0][2 * jj + 1], a0, b[2], b[3]);
                mma_f16(acc[1][2 * jj],     a1, b[0], b[1]);
                mma_f16(acc[1][2 * jj + 1], a1, b[2], b[3]);
            }
        }
    }

    // Epilogue: e = dot*2C - xn*C - dn*C ; sum exp over this warp's 64 cols.
    const float* dnsS = (const float*)(smem + SO_DNS);
    #pragma unroll
    for (int mi = 0; mi < 2; mi++) {
        const int r0 = rowBase + wm * 32 + mi * 16 + (lane >> 2);
        const float xn0 = -g_xn[r0] * CC;
        const float xn1 = -g_xn[r0 + 8] * CC;
        float s0 = 0.f, s1 = 0.f;
        #pragma unroll
        for (int jn = 0; jn < 8; jn++) {
            const int cb = wn * 64 + jn * 8 + 2 * (lane & 3);
            const float d0 = dnsS[cb], d1 = dnsS[cb + 1];
            s0 += __expf(fmaf(acc[mi][jn][0], 2.f * CC, xn0 + d0));
            s0 += __expf(fmaf(acc[mi][jn][1], 2.f * CC, xn0 + d1));
            s1 += __expf(fmaf(acc[mi][jn][2], 2.f * CC, xn1 + d0));
            s1 += __expf(fmaf(acc[mi][jn][3], 2.f * CC, xn1 + d1));
        }
        s0 += __shfl_xor_sync(0xFFFFFFFFu, s0, 1);
        s0 += __shfl_xor_sync(0xFFFFFFFFu, s0, 2);
        s1 += __shfl_xor_sync(0xFFFFFFFFu, s1, 1);
        s1 += __shfl_xor_sync(0xFFFFFFFFu, s1, 2);
        if ((lane & 3) == 0) {
            const size_t chunk = blockIdx.x * 4 + wn;   // 128 chunks total
            g_part[chunk * N + r0]     = s0;
            g_part[chunk * N + r0 + 8] = s1;
        }
    }
}

// ---------------------------------------------------------------------------
// Kernel 3: fixed-order reduction over 128 column chunks -> density.
// ---------------------------------------------------------------------------
__global__ void reduce_kernel(float* __restrict__ out, int N, int M, int nchunk) {
    int r = blockIdx.x * blockDim.x + threadIdx.x;
    if (r >= N) return;
    float s = 0.f;
    for (int t = 0; t < nchunk; t++) s += g_part[(size_t)t * N + r];
    out[r] = s * (1.0f / (float)M);
}

// ---------------------------------------------------------------------------
extern "C" void kernel_launch(void* const* d_in, const int* in_sizes, int n_in,
                              void* d_out, int out_size) {
    const float* x   = (const float*)d_in[0];
    const float* dat = (const float*)d_in[1];
    float* out = (float*)d_out;

    int N = in_sizes[0] / DDIM;   // 8192
    int M = in_sizes[1] / DDIM;   // 8192
    int R = (N > M) ? N : M;

    cudaFuncSetAttribute(kde_mma, cudaFuncAttributeMaxDynamicSharedMemorySize,
                         SMEMT);

    prep_kernel<<<(R * 32 + 255) / 256, 256>>>(x, dat, N, M);

    dim3 grid(M / BN, N / BM);    // (32, 64) = 2048 CTAs
    kde_mma<<<grid, 512, SMEMT>>>(N, M);

    reduce_kernel<<<(N + 255) / 256, 256>>>(out, N, M, M / 64);
}

// round 17
// speedup vs baseline: 5.5689x; 1.3823x over previous
#include <cuda_runtime.h>
#include <cuda_fp16.h>
#include <cstdint>

// KDE via plain fp16 mma.sync tensor-core GEMM (K=128, no split — fp16
// rounding error measured 66x inside the 1e-3 gate), double-buffered
// cp.async pipeline, fused exp epilogue, deterministic fixed-order
// reduction.
//
// density[n] = (1/M) * sum_m exp( (2*dot(x_n,d_m) - |x_n|^2 - |d_m|^2) * C )

#define DDIM   128
#define KAUG   128            // plain fp16, no split
#define BM     128            // x rows per CTA
#define BN     256            // data rows per CTA
#define BKB    64             // fp16 K per stage
#define NST    (KAUG / BKB)   // 2
#define PITCHB 144            // smem row pitch bytes (72 halfs)
#define MAXROWS 8192
#define MAXCHUNK 128

#define CC  0.19947114020071633897f    // 0.5 / sqrt(2*pi)

__device__ __align__(256) __half g_xa[MAXROWS * KAUG];  // 2.1 MB
__device__ __align__(256) __half g_da[MAXROWS * KAUG];
__device__ float g_xn[MAXROWS];
__device__ float g_dn[MAXROWS];
__device__ float g_part[MAXCHUNK * MAXROWS];

// ---------------------------------------------------------------------------
__device__ __forceinline__ uint32_t smem_u32(const void* p) {
    uint32_t a;
    asm("{ .reg .u64 t; cvta.to.shared.u64 t, %1; cvt.u32.u64 %0, t; }"
        : "=r"(a) : "l"(p));
    return a;
}
__device__ __forceinline__ void cp16(uint32_t dst, const void* src) {
    asm volatile("cp.async.cg.shared.global [%0], [%1], 16;"
                 :: "r"(dst), "l"(src) : "memory");
}
__device__ __forceinline__ void ldmx4(uint32_t* r, uint32_t addr) {
    asm volatile("ldmatrix.sync.aligned.m8n8.x4.shared.b16 {%0,%1,%2,%3}, [%4];"
                 : "=r"(r[0]), "=r"(r[1]), "=r"(r[2]), "=r"(r[3]) : "r"(addr));
}
__device__ __forceinline__ void mma_f16(float* c, const uint32_t* a,
                                        uint32_t b0, uint32_t b1) {
    asm volatile(
        "mma.sync.aligned.m16n8k16.row.col.f32.f16.f16.f32 "
        "{%0,%1,%2,%3}, {%4,%5,%6,%7}, {%8,%9}, {%0,%1,%2,%3};"
        : "+f"(c[0]), "+f"(c[1]), "+f"(c[2]), "+f"(c[3])
        : "r"(a[0]), "r"(a[1]), "r"(a[2]), "r"(a[3]), "r"(b0), "r"(b1));
}
__device__ __forceinline__ uint32_t packh2(float a, float b) {
    __half2 p = __floats2half2_rn(a, b);
    return *reinterpret_cast<uint32_t*>(&p);
}

// ---------------------------------------------------------------------------
// Kernel 1: fp16 conversion + exact fp32 row norms.
// One warp per row; lane handles one float4.
// ---------------------------------------------------------------------------
__global__ __launch_bounds__(256)
void prep_kernel(const float* __restrict__ x, const float* __restrict__ dat,
                 int N, int M) {
    int w = (blockIdx.x * blockDim.x + threadIdx.x) >> 5;
    int lane = threadIdx.x & 31;
    int R = (N > M) ? N : M;
    if (w >= R) return;

    #pragma unroll
    for (int which = 0; which < 2; which++) {
        if ((which ? M : N) <= w) continue;
        const float* src = which ? dat : x;
        float4 v = ((const float4*)(src + (size_t)w * DDIM))[lane];

        uint2 hi = make_uint2(packh2(v.x, v.y), packh2(v.z, v.w));
        uint2* dst = (uint2*)((which ? g_da : g_xa) + (size_t)w * KAUG) + lane;
        dst[0] = hi;

        float s = v.x * v.x + v.y * v.y + v.z * v.z + v.w * v.w;
        #pragma unroll
        for (int o = 16; o > 0; o >>= 1) s += __shfl_down_sync(0xFFFFFFFFu, s, o);
        if (lane == 0) { if (which) g_dn[w] = s; else g_xn[w] = s; }
    }
}

// ---------------------------------------------------------------------------
// Kernel 2: 128x256 tile per CTA, 512 threads = 16 warps (4 M x 4 N),
// warp tile 32x64. Double-buffered cp.async (both stages prefetched).
// ---------------------------------------------------------------------------
#define SO_DNS 0
#define SA_BYTES (128 * PITCHB)            // 18432
#define SB_BYTES (256 * PITCHB)            // 36864
#define SO_A   1024
#define SO_B   (SO_A + 2 * SA_BYTES)       // 37888
#define SMEMT  (SO_B + 2 * SB_BYTES)       // 111616 B

__global__ __launch_bounds__(512, 1)
void kde_mma(int N, int M) {
    extern __shared__ char smem[];
    const uint32_t sb = smem_u32(smem);
    const int tid = threadIdx.x, lane = tid & 31, w = tid >> 5;
    const int wm = w >> 2, wn = w & 3;
    const int rowBase = blockIdx.y * BM;
    const int colBase = blockIdx.x * BN;

    if (tid < 256)
        *(float*)(smem + SO_DNS + tid * 4) = -g_dn[colBase + tid] * CC;

    const __half* Ag = g_xa + (size_t)rowBase * KAUG;
    const __half* Bg = g_da + (size_t)colBase * KAUG;

    float acc[2][8][4];
    #pragma unroll
    for (int i = 0; i < 2; i++)
        #pragma unroll
        for (int j = 0; j < 8; j++)
            #pragma unroll
            for (int c = 0; c < 4; c++) acc[i][j][c] = 0.f;

    // ldmatrix lane address bases (buffer 0)
    const int bq = lane >> 3, rr = lane & 7;
    const uint32_t aAddr0 = sb + SO_A +
        (uint32_t)((wm * 32 + (bq & 1) * 8 + rr) * PITCHB) + (uint32_t)((lane >> 4) * 16);
    const uint32_t bAddr0 = sb + SO_B +
        (uint32_t)((wn * 64 + (lane >> 4) * 8 + rr) * PITCHB) + (uint32_t)((bq & 1) * 16);

    // cp.async stage issue: A = 1024 x16B (2/thread), B = 2048 x16B (4/thread)
    auto issue = [&](int s) {
        const int kb = s * BKB;
        const int buf = s & 1;
        const uint32_t ab = sb + SO_A + buf * SA_BYTES;
        const uint32_t bb = sb + SO_B + buf * SB_BYTES;
        #pragma unroll
        for (int i = 0; i < 2; i++) {
            int f = tid + i * 512, r = f >> 3, q = f & 7;
            cp16(ab + r * PITCHB + q * 16, Ag + (size_t)r * KAUG + kb + q * 8);
        }
        #pragma unroll
        for (int i = 0; i < 4; i++) {
            int f = tid + i * 512, r = f >> 3, q = f & 7;
            cp16(bb + r * PITCHB + q * 16, Bg + (size_t)r * KAUG + kb + q * 8);
        }
        asm volatile("cp.async.commit_group;" ::: "memory");
    };

    issue(0);
    issue(1);
    #pragma unroll
    for (int s = 0; s < NST; s++) {
        if (s < NST - 1)
            asm volatile("cp.async.wait_group 1;" ::: "memory");
        else
            asm volatile("cp.async.wait_group 0;" ::: "memory");
        __syncthreads();

        const int buf = s & 1;
        const uint32_t ab = aAddr0 + buf * SA_BYTES;
        const uint32_t bb = bAddr0 + buf * SB_BYTES;
        #pragma unroll
        for (int k4 = 0; k4 < BKB / 16; k4++) {      // 4 k16 steps
            uint32_t a0[4], a1[4];
            ldmx4(a0, ab + k4 * 32);                 // m rows +0..15
            ldmx4(a1, ab + 16 * PITCHB + k4 * 32);   // m rows +16..31
            #pragma unroll
            for (int jj = 0; jj < 4; jj++) {         // 16 n each
                uint32_t b[4];
                ldmx4(b, bb + jj * 16 * PITCHB + k4 * 32);
                mma_f16(acc[0][2 * jj],     a0, b[0], b[1]);
                mma_f16(acc[0][2 * jj + 1], a0, b[2], b[3]);
                mma_f16(acc[1][2 * jj],     a1, b[0], b[1]);
                mma_f16(acc[1][2 * jj + 1], a1, b[2], b[3]);
            }
        }
    }

    // Epilogue: e = dot*2C - xn*C - dn*C ; sum exp over this warp's 64 cols.
    const float* dnsS = (const float*)(smem + SO_DNS);
    #pragma unroll
    for (int mi = 0; mi < 2; mi++) {
        const int r0 = rowBase + wm * 32 + mi * 16 + (lane >> 2);
        const float xn0 = -g_xn[r0] * CC;
        const float xn1 = -g_xn[r0 + 8] * CC;
        float s0 = 0.f, s1 = 0.f;
        #pragma unroll
        for (int jn = 0; jn < 8; jn++) {
            const int cb = wn * 64 + jn * 8 + 2 * (lane & 3);
            const float d0 = dnsS[cb], d1 = dnsS[cb + 1];
            s0 += __expf(fmaf(acc[mi][jn][0], 2.f * CC, xn0 + d0));
            s0 += __expf(fmaf(acc[mi][jn][1], 2.f * CC, xn0 + d1));
            s1 += __expf(fmaf(acc[mi][jn][2], 2.f * CC, xn1 + d0));
            s1 += __expf(fmaf(acc[mi][jn][3], 2.f * CC, xn1 + d1));
        }
        s0 += __shfl_xor_sync(0xFFFFFFFFu, s0, 1);
        s0 += __shfl_xor_sync(0xFFFFFFFFu, s0, 2);
        s1 += __shfl_xor_sync(0xFFFFFFFFu, s1, 1);
        s1 += __shfl_xor_sync(0xFFFFFFFFu, s1, 2);
        if ((lane & 3) == 0) {
            const size_t chunk = blockIdx.x * 4 + wn;   // 128 chunks total
            g_part[chunk * N + r0]     = s0;
            g_part[chunk * N + r0 + 8] = s1;
        }
    }
}

// ---------------------------------------------------------------------------
// Kernel 3: fixed-order reduction over 128 column chunks -> density.
// ---------------------------------------------------------------------------
__global__ void reduce_kernel(float* __restrict__ out, int N, int M, int nchunk) {
    int r = blockIdx.x * blockDim.x + threadIdx.x;
    if (r >= N) return;
    float s = 0.f;
    for (int t = 0; t < nchunk; t++) s += g_part[(size_t)t * N + r];
    out[r] = s * (1.0f / (float)M);
}

// ---------------------------------------------------------------------------
extern "C" void kernel_launch(void* const* d_in, const int* in_sizes, int n_in,
                              void* d_out, int out_size) {
    const float* x   = (const float*)d_in[0];
    const float* dat = (const float*)d_in[1];
    float* out = (float*)d_out;

    int N = in_sizes[0] / DDIM;   // 8192
    int M = in_sizes[1] / DDIM;   // 8192
    int R = (N > M) ? N : M;

    cudaFuncSetAttribute(kde_mma, cudaFuncAttributeMaxDynamicSharedMemorySize,
                         SMEMT);

    prep_kernel<<<(R * 32 + 255) / 256, 256>>>(x, dat, N, M);

    dim3 grid(M / BN, N / BM);    // (32, 64) = 2048 CTAs
    kde_mma<<<grid, 512, SMEMT>>>(N, M);

    reduce_kernel<<<(N + 255) / 256, 256>>>(out, N, M, M / 64);
}